// round 1
// baseline (speedup 1.0000x reference)
#include <cuda_runtime.h>
#include <cstdint>

// Problem constants (fixed shapes from reference)
#define B_SZ 4096
#define I_SZ 1024
#define H_SZ 2048
#define NSTEPS 5
#define DT_C 0.1f

// ---------------- scratch (static device globals; no runtime alloc) --------
__device__ float g_C1[B_SZ * H_SZ];   // input_contrib = x@W_in_w^T + b
__device__ float g_C2[B_SZ * H_SZ];   // x_tau + tau_adapt_b
__device__ float g_G1[B_SZ * H_SZ];   // h @ Wth^T
__device__ float g_G2[B_SZ * H_SZ];   // h @ W_rec^T
__device__ float g_h [B_SZ * H_SZ];   // running hidden state

// ---------------- tf32 helpers ---------------------------------------------
__device__ __forceinline__ unsigned f2tf(float x) {
    unsigned y;
    asm("cvt.rna.tf32.f32 %0, %1;" : "=r"(y) : "f"(x));
    return y;
}

__device__ __forceinline__ void mma_tf32(float* d, const unsigned* a, const unsigned* b) {
    asm volatile(
        "mma.sync.aligned.m16n8k8.row.col.f32.tf32.tf32.f32 "
        "{%0,%1,%2,%3}, {%4,%5,%6,%7}, {%8,%9}, {%0,%1,%2,%3};"
        : "+f"(d[0]), "+f"(d[1]), "+f"(d[2]), "+f"(d[3])
        : "r"(a[0]), "r"(a[1]), "r"(a[2]), "r"(a[3]),
          "r"(b[0]), "r"(b[1]));
}

// ---------------- GEMM: C[M=4096, N=2048] = A[M,K] @ B[N,K]^T (+bias) ------
// CTA tile 128x128, K-tile 16, tf32 mma m16n8k8.
// smem XOR swizzle (16B granularity): element (r,k) stored at word
//   r*16 + ((k>>2) ^ ((r>>1)&3))*4 + (k&3)   -> conflict-free frag loads.
#define BM 128
#define BN 128
#define BK 16

__global__ void __launch_bounds__(256)
gemm_tf32_kernel(const float* __restrict__ A, int lda,
                 const float* __restrict__ Bw, int ldb,
                 float* __restrict__ C,
                 const float* __restrict__ bias,
                 int K)
{
    __shared__ unsigned sA[2][BM * BK];
    __shared__ unsigned sB[2][BN * BK];

    const int tid  = threadIdx.x;
    const int lane = tid & 31;
    const int wid  = tid >> 5;
    const int wm   = (wid >> 2) * 64;   // warp row offset: 0 or 64
    const int wn   = (wid & 3)  * 32;   // warp col offset: 0..96
    const int grp  = lane >> 2;         // 0..7
    const int tig  = lane & 3;          // 0..3

    const int m0 = blockIdx.y * BM;
    const int n0 = blockIdx.x * BN;

    // loader mapping: thread covers rows lr and lr+64, 16B chunk lc4
    const int lr  = tid >> 2;           // 0..63
    const int lc4 = tid & 3;
    const int sws = ((lc4 ^ ((lr >> 1) & 3)) << 2);
    const int sOffLo = lr * BK + sws;
    const int sOffHi = (lr + 64) * BK + sws;  // same swizzle (64 ≡ 0 mod 4 after >>1)

    const float* gA0 = A  + (long)(m0 + lr) * lda + lc4 * 4;
    const float* gA1 = gA0 + (long)64 * lda;
    const float* gB0 = Bw + (long)(n0 + lr) * ldb + lc4 * 4;
    const float* gB1 = gB0 + (long)64 * ldb;

    float acc[4][4][4];
#pragma unroll
    for (int mt = 0; mt < 4; mt++)
#pragma unroll
        for (int nt = 0; nt < 4; nt++)
#pragma unroll
            for (int r = 0; r < 4; r++) acc[mt][nt][r] = 0.f;

    float4 rA0, rA1, rB0, rB1;

    auto LOAD = [&](int k0) {
        rA0 = *(const float4*)(gA0 + k0);
        rA1 = *(const float4*)(gA1 + k0);
        rB0 = *(const float4*)(gB0 + k0);
        rB1 = *(const float4*)(gB1 + k0);
    };
    auto STORE = [&](int buf) {
        uint4 u;
        u.x = f2tf(rA0.x); u.y = f2tf(rA0.y); u.z = f2tf(rA0.z); u.w = f2tf(rA0.w);
        *(uint4*)&sA[buf][sOffLo] = u;
        u.x = f2tf(rA1.x); u.y = f2tf(rA1.y); u.z = f2tf(rA1.z); u.w = f2tf(rA1.w);
        *(uint4*)&sA[buf][sOffHi] = u;
        u.x = f2tf(rB0.x); u.y = f2tf(rB0.y); u.z = f2tf(rB0.z); u.w = f2tf(rB0.w);
        *(uint4*)&sB[buf][sOffLo] = u;
        u.x = f2tf(rB1.x); u.y = f2tf(rB1.y); u.z = f2tf(rB1.z); u.w = f2tf(rB1.w);
        *(uint4*)&sB[buf][sOffHi] = u;
    };

    // fragment column word offsets per k-chunk c4 (swizzled), for this thread
    const int swf = (grp >> 1) & 3;
    int colk[4];
#pragma unroll
    for (int c4 = 0; c4 < 4; c4++) colk[c4] = ((c4 ^ swf) << 2) + tig;

    auto COMPUTE = [&](int buf) {
#pragma unroll
        for (int ks = 0; ks < 2; ks++) {
            unsigned af[4][4];
            unsigned bf[4][2];
            const int cLo = colk[2 * ks];
            const int cHi = colk[2 * ks + 1];
#pragma unroll
            for (int mt = 0; mt < 4; mt++) {
                int rbase = (wm + mt * 16 + grp) * BK;
                af[mt][0] = sA[buf][rbase + cLo];
                af[mt][1] = sA[buf][rbase + 8 * BK + cLo];
                af[mt][2] = sA[buf][rbase + cHi];
                af[mt][3] = sA[buf][rbase + 8 * BK + cHi];
            }
#pragma unroll
            for (int nt = 0; nt < 4; nt++) {
                int rbase = (wn + nt * 8 + grp) * BK;
                bf[nt][0] = sB[buf][rbase + cLo];
                bf[nt][1] = sB[buf][rbase + cHi];
            }
#pragma unroll
            for (int mt = 0; mt < 4; mt++)
#pragma unroll
                for (int nt = 0; nt < 4; nt++)
                    mma_tf32(acc[mt][nt], af[mt], bf[nt]);
        }
    };

    // pipeline: register-staged double buffering
    LOAD(0);
    STORE(0);
    __syncthreads();
    const int nK = K / BK;
    for (int kt = 0; kt < nK; kt++) {
        const int buf = kt & 1;
        if (kt + 1 < nK) LOAD((kt + 1) * BK);
        COMPUTE(buf);
        if (kt + 1 < nK) {
            __syncthreads();
            STORE(buf ^ 1);
            __syncthreads();
        }
    }

    // epilogue (+ optional bias indexed by output column)
#pragma unroll
    for (int mt = 0; mt < 4; mt++) {
        const int row = m0 + wm + mt * 16 + grp;
#pragma unroll
        for (int nt = 0; nt < 4; nt++) {
            const int col = n0 + wn + nt * 8 + 2 * tig;
            float b0 = 0.f, b1 = 0.f;
            if (bias) { b0 = __ldg(bias + col); b1 = __ldg(bias + col + 1); }
            float2 v0, v1;
            v0.x = acc[mt][nt][0] + b0; v0.y = acc[mt][nt][1] + b1;
            v1.x = acc[mt][nt][2] + b0; v1.y = acc[mt][nt][3] + b1;
            *(float2*)&C[(long)row * H_SZ + col]       = v0;
            *(float2*)&C[(long)(row + 8) * H_SZ + col] = v1;
        }
    }
}

// ---------------- elementwise liquid step ----------------------------------
__global__ void __launch_bounds__(256)
liquid_step_kernel(const float* __restrict__ h_in,
                   const float* __restrict__ G1,
                   const float* __restrict__ G2,
                   const float* __restrict__ C1,
                   const float* __restrict__ C2,
                   const float* __restrict__ tau_base,
                   float* __restrict__ h_out,
                   float* __restrict__ tau_out)
{
    const int idx = (blockIdx.x * 256 + threadIdx.x) * 4;
    const int j = idx & (H_SZ - 1);

    float4 g1 = *(const float4*)(G1 + idx);
    float4 g2 = *(const float4*)(G2 + idx);
    float4 c1 = *(const float4*)(C1 + idx);
    float4 c2 = *(const float4*)(C2 + idx);
    float4 hv = *(const float4*)(h_in + idx);
    float4 tb = *(const float4*)(tau_base + j);

    float4 hn, tv;
#define ONE_LANE(f)                                                        \
    {                                                                      \
        float tl  = c2.f + g1.f;                                           \
        float sg  = 1.f / (1.f + expf(-tl));                               \
        float tau = tb.f * (0.5f + sg);                                    \
        float act = tanhf(g2.f + c1.f);                                    \
        hn.f = hv.f + DT_C * (act - hv.f) / tau;                           \
        tv.f = tau;                                                        \
    }
    ONE_LANE(x) ONE_LANE(y) ONE_LANE(z) ONE_LANE(w)
#undef ONE_LANE

    *(float4*)(h_out + idx) = hn;
    if (tau_out) *(float4*)(tau_out + idx) = tv;
}

// ---------------- launcher --------------------------------------------------
extern "C" void kernel_launch(void* const* d_in, const int* in_sizes, int n_in,
                              void* d_out, int out_size)
{
    (void)in_sizes; (void)n_in; (void)out_size;

    const float* x           = (const float*)d_in[0];
    const float* hidden      = (const float*)d_in[1];
    const float* W_rec       = (const float*)d_in[2];
    const float* W_in_w      = (const float*)d_in[3];
    const float* W_in_b      = (const float*)d_in[4];
    const float* tau_base    = (const float*)d_in[5];
    const float* tau_adapt_w = (const float*)d_in[6];
    const float* tau_adapt_b = (const float*)d_in[7];

    float* out_h   = (float*)d_out;
    float* out_tau = out_h + (long)B_SZ * H_SZ;

    float *C1, *C2, *G1, *G2, *hbuf;
    cudaGetSymbolAddress((void**)&C1,   g_C1);
    cudaGetSymbolAddress((void**)&C2,   g_C2);
    cudaGetSymbolAddress((void**)&G1,   g_G1);
    cudaGetSymbolAddress((void**)&G2,   g_G2);
    cudaGetSymbolAddress((void**)&hbuf, g_h);

    dim3 gg(H_SZ / BN, B_SZ / BM);   // (16, 32)
    const int ldtau = I_SZ + H_SZ;   // 3072

    // loop-invariant GEMMs (biases folded in once)
    gemm_tf32_kernel<<<gg, 256>>>(x, I_SZ, W_in_w, I_SZ, C1, W_in_b, I_SZ);
    gemm_tf32_kernel<<<gg, 256>>>(x, I_SZ, tau_adapt_w, ldtau, C2, tau_adapt_b, I_SZ);

    const float* h = hidden;
    const int n_ew = (B_SZ * H_SZ) / 4 / 256;   // 8192 blocks
    for (int s = 0; s < NSTEPS; s++) {
        gemm_tf32_kernel<<<gg, 256>>>(h, H_SZ, tau_adapt_w + I_SZ, ldtau, G1, nullptr, H_SZ);
        gemm_tf32_kernel<<<gg, 256>>>(h, H_SZ, W_rec, H_SZ, G2, nullptr, H_SZ);

        float* ho = (s == NSTEPS - 1) ? out_h   : hbuf;
        float* to = (s == NSTEPS - 1) ? out_tau : nullptr;
        liquid_step_kernel<<<n_ew, 256>>>(h, G1, G2, C1, C2, tau_base, ho, to);
        h = hbuf;
    }
}

// round 4
// speedup vs baseline: 1.5585x; 1.5585x over previous
#include <cuda_runtime.h>
#include <cstdint>

// -------------------- problem constants --------------------
#define B_SZ 4096
#define I_SZ 1024
#define H_SZ 2048
#define NSTEPS 5
#define DT_C 0.1f

// -------------------- GEMM tiling --------------------
#define BM 128
#define BN 256
#define BK 16
#define NSTAGE 4
#define THREADS 256

#define SA_BYTES (BM * BK * 4)                 // 8192
#define SB_BYTES (BN * BK * 4)                 // 16384
#define STAGE_BYTES (SA_BYTES + SB_BYTES)      // 24576
#define SMEM_TOTAL (NSTAGE * STAGE_BYTES)      // 98304

// -------------------- scratch --------------------
__device__ float g_C1[B_SZ * H_SZ];
__device__ float g_C2[B_SZ * H_SZ];
__device__ float g_G1[B_SZ * H_SZ];
__device__ float g_G2[B_SZ * H_SZ];
__device__ float g_h [B_SZ * H_SZ];

// -------------------- PTX helpers --------------------
__device__ __forceinline__ void cp16(uint32_t smem, const void* g) {
    asm volatile("cp.async.cg.shared.global [%0], [%1], 16;" :: "r"(smem), "l"(g) : "memory");
}
__device__ __forceinline__ void cp_commit() {
    asm volatile("cp.async.commit_group;" ::: "memory");
}
template <int N>
__device__ __forceinline__ void cp_wait() {
    asm volatile("cp.async.wait_group %0;" :: "n"(N) : "memory");
}
__device__ __forceinline__ void ldsm4(uint32_t* r, uint32_t a) {
    asm volatile("ldmatrix.sync.aligned.m8n8.x4.shared.b16 {%0,%1,%2,%3}, [%4];"
                 : "=r"(r[0]), "=r"(r[1]), "=r"(r[2]), "=r"(r[3]) : "r"(a));
}
__device__ __forceinline__ void mma_tf32(float* d, const uint32_t* a, const uint32_t* b) {
    asm volatile(
        "mma.sync.aligned.m16n8k8.row.col.f32.tf32.tf32.f32 "
        "{%0,%1,%2,%3}, {%4,%5,%6,%7}, {%8,%9}, {%0,%1,%2,%3};"
        : "+f"(d[0]), "+f"(d[1]), "+f"(d[2]), "+f"(d[3])
        : "r"(a[0]), "r"(a[1]), "r"(a[2]), "r"(a[3]), "r"(b[0]), "r"(b[1]));
}

// swizzled smem byte address for 16B chunk (row r of 64B, chunk g of 4)
__device__ __forceinline__ uint32_t swadr(uint32_t base, int r, int g) {
    const int c = g ^ (r & 3) ^ ((r >> 2) & 1);
    return base + (uint32_t)(r * 64 + c * 16);
}

// -------------------- dual-B tf32 GEMM --------------------
// C_half[M, H_SZ]: tile = A[m0:+128, :K] @ Bh[n0:+256, :K]^T (+bias_h)
// grid (16, M/128): blockIdx.x selects half (B0->C0 or B1->C1) and n-block.
__global__ void __launch_bounds__(THREADS, 1)
gemm_dual_tf32(const float* __restrict__ A, int lda,
               const float* __restrict__ B0, int ldb0, float* __restrict__ C0,
               const float* __restrict__ bias0,
               const float* __restrict__ B1, int ldb1, float* __restrict__ C1,
               const float* __restrict__ bias1,
               int K)
{
    extern __shared__ __align__(1024) char smem[];
    const uint32_t sb = (uint32_t)__cvta_generic_to_shared(smem);

    const int tid  = threadIdx.x;
    const int lane = tid & 31;
    const int wid  = tid >> 5;
    const int wm   = (wid >> 2) * 64;     // warp row base: 0 / 64
    const int wn   = (wid & 3) * 64;      // warp col base: 0..192

    const int half = blockIdx.x >> 3;
    const int nblk = blockIdx.x & 7;
    const int m0 = blockIdx.y * BM;
    const int n0 = nblk * BN;

    const float* Bw   = half ? B1 : B0;
    const int    ldb  = half ? ldb1 : ldb0;
    float*       C    = half ? C1 : C0;
    const float* bias = half ? bias1 : bias0;

    // ---- loader coordinates ----
    const int lr = tid >> 2;      // 0..63
    const int lg = tid & 3;       // chunk 0..3
    const float* gA = A  + (long)(m0 + lr) * lda + lg * 4;
    const float* gB = Bw + (long)(n0 + lr) * ldb + lg * 4;
    const long strideA64 = (long)64 * lda;
    const long strideB64 = (long)64 * ldb;

    // ---- ldmatrix lane coordinates ----
    const int arow = (lane & 7) + ((lane >> 3) & 1) * 8;   // row within 16-block
    const int agof = (lane >> 4);                          // +0/+1 k-group
    const int brow = (lane & 7) + ((lane >> 4) & 1) * 8;
    const int bgof = (lane >> 3) & 1;

    float acc[4][8][4];
#pragma unroll
    for (int mt = 0; mt < 4; mt++)
#pragma unroll
        for (int nt = 0; nt < 8; nt++)
#pragma unroll
            for (int r = 0; r < 4; r++) acc[mt][nt][r] = 0.f;

    const int nK = K / BK;

    // ---- stage loader (6 cp.async per thread) ----
    // NOTE: gA/gB already include the +lg*4 column offset; koff is k-tile only.
    auto load_stage = [&](int s, int kt) {
        const uint32_t sA = sb + s * STAGE_BYTES;
        const uint32_t sB = sA + SA_BYTES;
        const int koff = kt * BK;
        cp16(swadr(sA, lr,       lg), gA + koff);
        cp16(swadr(sA, lr + 64,  lg), gA + koff + strideA64);
        cp16(swadr(sB, lr,       lg), gB + koff);
        cp16(swadr(sB, lr + 64,  lg), gB + koff + strideB64);
        cp16(swadr(sB, lr + 128, lg), gB + koff + 2 * strideB64);
        cp16(swadr(sB, lr + 192, lg), gB + koff + 3 * strideB64);
    };

    // prologue: prefetch NSTAGE-1 stages
#pragma unroll
    for (int s = 0; s < NSTAGE - 1; s++) {
        load_stage(s, s);
        cp_commit();
    }

    for (int kt = 0; kt < nK; kt++) {
        cp_wait<NSTAGE - 2>();
        __syncthreads();

        const int kload = kt + NSTAGE - 1;
        if (kload < nK) load_stage(kload & (NSTAGE - 1), kload);
        cp_commit();

        const uint32_t sA = sb + (kt & (NSTAGE - 1)) * STAGE_BYTES;
        const uint32_t sB = sA + SA_BYTES;

#pragma unroll
        for (int ks = 0; ks < 2; ks++) {
            uint32_t af[4][4], bf[4][4];
#pragma unroll
            for (int mt = 0; mt < 4; mt++)
                ldsm4(af[mt], swadr(sA, wm + mt * 16 + arow, 2 * ks + agof));
#pragma unroll
            for (int p = 0; p < 4; p++)
                ldsm4(bf[p], swadr(sB, wn + p * 16 + brow, 2 * ks + bgof));
#pragma unroll
            for (int mt = 0; mt < 4; mt++)
#pragma unroll
                for (int p = 0; p < 4; p++) {
                    mma_tf32(acc[mt][2 * p],     af[mt], &bf[p][0]);
                    mma_tf32(acc[mt][2 * p + 1], af[mt], &bf[p][2]);
                }
        }
    }

    // ---- epilogue ----
    const int grp = lane >> 2;
    const int tig = lane & 3;
#pragma unroll
    for (int mt = 0; mt < 4; mt++) {
        const int row0 = m0 + wm + mt * 16 + grp;
#pragma unroll
        for (int nt = 0; nt < 8; nt++) {
            const int col = n0 + wn + nt * 8 + 2 * tig;
            float b0 = 0.f, b1 = 0.f;
            if (bias) { b0 = __ldg(bias + col); b1 = __ldg(bias + col + 1); }
            float2 v0, v1;
            v0.x = acc[mt][nt][0] + b0; v0.y = acc[mt][nt][1] + b1;
            v1.x = acc[mt][nt][2] + b0; v1.y = acc[mt][nt][3] + b1;
            *(float2*)(C + (long)row0 * H_SZ + col)       = v0;
            *(float2*)(C + (long)(row0 + 8) * H_SZ + col) = v1;
        }
    }
}

// -------------------- elementwise liquid step --------------------
__global__ void __launch_bounds__(256)
liquid_step_kernel(const float* __restrict__ h_in,
                   const float* __restrict__ G1,
                   const float* __restrict__ G2,
                   const float* __restrict__ C1,
                   const float* __restrict__ C2,
                   const float* __restrict__ tau_base,
                   float* __restrict__ h_out,
                   float* __restrict__ tau_out)
{
    const int idx = (blockIdx.x * 256 + threadIdx.x) * 4;
    const int j = idx & (H_SZ - 1);

    float4 g1 = *(const float4*)(G1 + idx);
    float4 g2 = *(const float4*)(G2 + idx);
    float4 c1 = *(const float4*)(C1 + idx);
    float4 c2 = *(const float4*)(C2 + idx);
    float4 hv = *(const float4*)(h_in + idx);
    float4 tb = *(const float4*)(tau_base + j);

    float4 hn, tv;
#define ONE_LANE(f)                                                        \
    {                                                                      \
        float tl  = c2.f + g1.f;                                           \
        float sg  = 1.f / (1.f + expf(-tl));                               \
        float tau = tb.f * (0.5f + sg);                                    \
        float act = tanhf(g2.f + c1.f);                                    \
        hn.f = hv.f + DT_C * (act - hv.f) / tau;                           \
        tv.f = tau;                                                        \
    }
    ONE_LANE(x) ONE_LANE(y) ONE_LANE(z) ONE_LANE(w)
#undef ONE_LANE

    *(float4*)(h_out + idx) = hn;
    if (tau_out) *(float4*)(tau_out + idx) = tv;
}

// -------------------- launcher --------------------
extern "C" void kernel_launch(void* const* d_in, const int* in_sizes, int n_in,
                              void* d_out, int out_size)
{
    (void)in_sizes; (void)n_in; (void)out_size;

    const float* x           = (const float*)d_in[0];
    const float* hidden      = (const float*)d_in[1];
    const float* W_rec       = (const float*)d_in[2];
    const float* W_in_w      = (const float*)d_in[3];
    const float* W_in_b      = (const float*)d_in[4];
    const float* tau_base    = (const float*)d_in[5];
    const float* tau_adapt_w = (const float*)d_in[6];
    const float* tau_adapt_b = (const float*)d_in[7];

    float* out_h   = (float*)d_out;
    float* out_tau = out_h + (long)B_SZ * H_SZ;

    float *C1, *C2, *G1, *G2, *hbuf;
    cudaGetSymbolAddress((void**)&C1,   g_C1);
    cudaGetSymbolAddress((void**)&C2,   g_C2);
    cudaGetSymbolAddress((void**)&G1,   g_G1);
    cudaGetSymbolAddress((void**)&G2,   g_G2);
    cudaGetSymbolAddress((void**)&hbuf, g_h);

    cudaFuncSetAttribute(gemm_dual_tf32, cudaFuncAttributeMaxDynamicSharedMemorySize, SMEM_TOTAL);

    const int ldtau = I_SZ + H_SZ;     // 3072
    dim3 gg(16, B_SZ / BM);            // 16 x 32 = 512 CTAs

    // invariant GEMMs fused: C1 = x@W_in^T + b, C2 = x@tau_x^T + tb
    gemm_dual_tf32<<<gg, THREADS, SMEM_TOTAL>>>(
        x, I_SZ,
        W_in_w, I_SZ, C1, W_in_b,
        tau_adapt_w, ldtau, C2, tau_adapt_b,
        I_SZ);

    const float* h = hidden;
    const int n_ew = (B_SZ * H_SZ) / 4 / 256;
    for (int s = 0; s < NSTEPS; s++) {
        // in-loop GEMMs fused: G1 = h@tau_h^T, G2 = h@W_rec^T
        gemm_dual_tf32<<<gg, THREADS, SMEM_TOTAL>>>(
            h, H_SZ,
            tau_adapt_w + I_SZ, ldtau, G1, nullptr,
            W_rec, H_SZ, G2, nullptr,
            H_SZ);

        float* ho = (s == NSTEPS - 1) ? out_h   : hbuf;
        float* to = (s == NSTEPS - 1) ? out_tau : nullptr;
        liquid_step_kernel<<<n_ew, 256>>>(h, G1, G2, C1, C2, tau_base, ho, to);
        h = hbuf;
    }
}